// round 1
// baseline (speedup 1.0000x reference)
#include <cuda_runtime.h>

// DirectVoxGO volume rendering composite:
//   log(1-alpha_i) = -interval * softplus(density_i + shift)
//   T_i = exclusive per-ray cumprod(1-alpha)
//   out[r] = sum_i alpha_i*T_i*rgb_i + T_last*bg
//
// Kernel 1: build per-ray start offsets from sorted ray_id (lower_bound table).
// Kernel 2: one warp per ray, 32-wide chunks, log2-space warp scan.

#define MAX_RAYS ((1 << 20))
__device__ int g_offsets[MAX_RAYS + 2];

__device__ __forceinline__ float f_ex2(float x) {
    float y; asm("ex2.approx.ftz.f32 %0, %1;" : "=f"(y) : "f"(x)); return y;
}
__device__ __forceinline__ float f_lg2(float x) {
    float y; asm("lg2.approx.ftz.f32 %0, %1;" : "=f"(y) : "f"(x)); return y;
}

__global__ void build_offsets_kernel(const int* __restrict__ ray_id, int M, int n_rays) {
    int i = blockIdx.x * blockDim.x + threadIdx.x;
    if (i >= M) return;
    int cur = ray_id[i];
    int prev = (i == 0) ? -1 : ray_id[i - 1];
    // all rays in (prev, cur] start at sample i (empty rays get start==end)
    for (int r = prev + 1; r <= cur; ++r) g_offsets[r] = i;
    if (i == M - 1) {
        for (int r = cur + 1; r <= n_rays; ++r) g_offsets[r] = M;
    }
}

__global__ void __launch_bounds__(256)
composite_kernel(const float* __restrict__ density,
                 const float* __restrict__ rgb,
                 const float* __restrict__ bg,
                 const float* __restrict__ p_shift,
                 const float* __restrict__ p_interval,
                 float* __restrict__ out,
                 int n_rays) {
    const int warp = (blockIdx.x * blockDim.x + threadIdx.x) >> 5;
    const int lane = threadIdx.x & 31;
    if (warp >= n_rays) return;

    const int start = g_offsets[warp];
    const int end   = g_offsets[warp + 1];

    const float shift = *p_shift;
    const float nInterval = -(*p_interval);
    const float L2E = 1.4426950408889634f;

    float carry = 0.f;          // running log2(T) (same in all lanes)
    float ar = 0.f, ag = 0.f, ab = 0.f;

    for (int base = start; base < end; base += 32) {
        const int idx = base + lane;
        const bool valid = (idx < end);

        float l2t = 0.f;        // log2(1 - alpha) for this sample
        float alpha = 0.f;
        if (valid) {
            float x = density[idx] + shift;
            float e = f_ex2(x * L2E);                 // exp(x)
            l2t = nInterval * f_lg2(1.f + e);         // -interval*log2(1+e^x)
            alpha = 1.f - f_ex2(l2t);
        }

        // warp-inclusive scan of l2t
        float inc = l2t;
        #pragma unroll
        for (int off = 1; off < 32; off <<= 1) {
            float v = __shfl_up_sync(0xffffffffu, inc, off);
            if (lane >= off) inc += v;
        }

        const float T = f_ex2(carry + (inc - l2t));   // exclusive transmittance
        const float w = alpha * T;

        if (valid) {
            const float* c = rgb + 3 * idx;
            ar = fmaf(w, c[0], ar);
            ag = fmaf(w, c[1], ag);
            ab = fmaf(w, c[2], ab);
        }
        carry += __shfl_sync(0xffffffffu, inc, 31);
    }

    // warp reduction of accumulated rgb
    #pragma unroll
    for (int off = 16; off; off >>= 1) {
        ar += __shfl_xor_sync(0xffffffffu, ar, off);
        ag += __shfl_xor_sync(0xffffffffu, ag, off);
        ab += __shfl_xor_sync(0xffffffffu, ab, off);
    }

    if (lane == 0) {
        const float Tlast = f_ex2(carry);             // final transmittance
        out[3 * warp + 0] = ar + Tlast * bg[0];
        out[3 * warp + 1] = ag + Tlast * bg[1];
        out[3 * warp + 2] = ab + Tlast * bg[2];
    }
}

extern "C" void kernel_launch(void* const* d_in, const int* in_sizes, int n_in,
                              void* d_out, int out_size) {
    // metadata order: density, rgb, bg, shift, interval, ray_id, n_rays
    const float* density    = (const float*)d_in[0];
    const float* rgb        = (const float*)d_in[1];
    const float* bg         = (const float*)d_in[2];
    const float* p_shift    = (const float*)d_in[3];
    const float* p_interval = (const float*)d_in[4];
    const int*   ray_id     = (const int*)d_in[5];

    const int M      = in_sizes[0];
    const int n_rays = out_size / 3;
    float* out = (float*)d_out;

    {
        int threads = 256;
        int blocks = (M + threads - 1) / threads;
        build_offsets_kernel<<<blocks, threads>>>(ray_id, M, n_rays);
    }
    {
        int threads = 256;                       // 8 warps -> 8 rays per block
        int blocks = (n_rays * 32 + threads - 1) / threads;
        composite_kernel<<<blocks, threads>>>(density, rgb, bg, p_shift,
                                              p_interval, out, n_rays);
    }
}

// round 3
// speedup vs baseline: 1.3486x; 1.3486x over previous
#include <cuda_runtime.h>

// DirectVoxGO volume rendering composite, R2:
//   log2(1-alpha_i) = -interval * log2(1 + exp(density_i + shift))
//   w_i = alpha_i * T_i = P_{i-1} - P_i,  P_i = 2^(per-ray inclusive prefix of log2(1-alpha))
//   out[r] = sum w_i rgb_i + P_last * bg
//
// Kernel 1: per-ray start offsets from sorted ray_id (int4 vectorized).
// Kernel 2: one warp per ray, 4 samples/thread (128/chunk), log2-space scan.

#define MAX_RAYS ((1 << 20))
__device__ int g_offsets[MAX_RAYS + 2];

__device__ __forceinline__ float f_ex2(float x) {
    float y; asm("ex2.approx.ftz.f32 %0, %1;" : "=f"(y) : "f"(x)); return y;
}
__device__ __forceinline__ float f_lg2(float x) {
    float y; asm("lg2.approx.ftz.f32 %0, %1;" : "=f"(y) : "f"(x)); return y;
}

// ---- Phase 1: offsets table (M assumed divisible by 4; guarded otherwise) ----
__global__ void __launch_bounds__(256)
build_offsets_vec4(const int* __restrict__ ray_id, int M, int n_rays) {
    const int i = blockIdx.x * blockDim.x + threadIdx.x;   // vec4 index
    const int e0 = i * 4;
    if (e0 >= M) return;

    int4 v = reinterpret_cast<const int4*>(ray_id)[i];
    int prev = (e0 == 0) ? -1 : __ldg(&ray_id[e0 - 1]);

    int vals[4] = {v.x, v.y, v.z, v.w};
    #pragma unroll
    for (int j = 0; j < 4; ++j) {
        int cur = vals[j];
        if (cur != prev) {
            for (int r = prev + 1; r <= cur; ++r) g_offsets[r] = e0 + j;
        }
        prev = cur;
    }
    if (e0 + 3 == M - 1) {
        for (int r = prev + 1; r <= n_rays; ++r) g_offsets[r] = M;
    }
}

// tail-safe scalar version for M % 4 != 0 (not used for this shape, kept correct)
__global__ void build_offsets_tail(const int* __restrict__ ray_id, int M, int n_rays, int from) {
    int i = from + blockIdx.x * blockDim.x + threadIdx.x;
    if (i >= M) return;
    int cur = ray_id[i];
    int prev = (i == 0) ? -1 : ray_id[i - 1];
    for (int r = prev + 1; r <= cur; ++r) g_offsets[r] = i;
    if (i == M - 1)
        for (int r = cur + 1; r <= n_rays; ++r) g_offsets[r] = M;
}

// ---- Phase 2: one warp per ray, 4 samples per thread ----
__global__ void __launch_bounds__(256)
composite_kernel(const float* __restrict__ density,
                 const float* __restrict__ rgb,
                 const float* __restrict__ bg,
                 const float* __restrict__ p_shift,
                 const float* __restrict__ p_interval,
                 float* __restrict__ out,
                 int n_rays) {
    const int warp = (blockIdx.x * blockDim.x + threadIdx.x) >> 5;
    const int lane = threadIdx.x & 31;
    if (warp >= n_rays) return;

    const int start = g_offsets[warp];
    const int end   = g_offsets[warp + 1];

    const float shift = *p_shift;
    const float nInterval = -(*p_interval);
    const float L2E = 1.4426950408889634f;

    float carry = 0.f;                 // running log2(T) at segment entry
    float ar = 0.f, ag = 0.f, ab = 0.f;

    for (int base = start; base < end; base += 128) {
        const int idx0 = base + lane * 4;

        // ---- load 4 densities + compute log2(1-alpha) per sample ----
        float l2t[4];
        #pragma unroll
        for (int j = 0; j < 4; ++j) {
            float lt = 0.f;
            if (idx0 + j < end) {
                float x = __ldg(&density[idx0 + j]) + shift;
                float e = f_ex2(x * L2E);                 // exp(x)
                lt = nInterval * f_lg2(1.f + e);          // log2(1-alpha) <= 0
            }
            l2t[j] = lt;
        }

        // ---- load rgb for the 4 samples (contiguous 12 floats) ----
        float cr[4], cg[4], cb[4];
        #pragma unroll
        for (int j = 0; j < 4; ++j) {
            if (idx0 + j < end) {
                const float* c = rgb + 3 * (idx0 + j);
                cr[j] = __ldg(&c[0]); cg[j] = __ldg(&c[1]); cb[j] = __ldg(&c[2]);
            } else { cr[j] = cg[j] = cb[j] = 0.f; }
        }

        // ---- thread-local inclusive prefix ----
        float s0 = l2t[0];
        float s1 = s0 + l2t[1];
        float s2 = s1 + l2t[2];
        float s3 = s2 + l2t[3];

        // ---- warp scan of thread totals ----
        float inc = s3;
        #pragma unroll
        for (int off = 1; off < 32; off <<= 1) {
            float v = __shfl_up_sync(0xffffffffu, inc, off);
            if (lane >= off) inc += v;
        }
        const float excl = carry + (inc - s3);            // log2 T entering this thread

        // ---- weights: w_j = P_{j-1} - P_j ----
        const float Pm1 = f_ex2(excl);
        const float P0  = f_ex2(excl + s0);
        const float P1  = f_ex2(excl + s1);
        const float P2  = f_ex2(excl + s2);
        const float P3  = f_ex2(excl + s3);

        ar = fmaf(Pm1 - P0, cr[0], ar);
        ag = fmaf(Pm1 - P0, cg[0], ag);
        ab = fmaf(Pm1 - P0, cb[0], ab);
        ar = fmaf(P0 - P1, cr[1], ar);
        ag = fmaf(P0 - P1, cg[1], ag);
        ab = fmaf(P0 - P1, cb[1], ab);
        ar = fmaf(P1 - P2, cr[2], ar);
        ag = fmaf(P1 - P2, cg[2], ag);
        ab = fmaf(P1 - P2, cb[2], ab);
        ar = fmaf(P2 - P3, cr[3], ar);
        ag = fmaf(P2 - P3, cg[3], ag);
        ab = fmaf(P2 - P3, cb[3], ab);

        carry += __shfl_sync(0xffffffffu, inc, 31);
    }

    // ---- warp reduction ----
    #pragma unroll
    for (int off = 16; off; off >>= 1) {
        ar += __shfl_xor_sync(0xffffffffu, ar, off);
        ag += __shfl_xor_sync(0xffffffffu, ag, off);
        ab += __shfl_xor_sync(0xffffffffu, ab, off);
    }

    if (lane == 0) {
        const float Tlast = f_ex2(carry);
        out[3 * warp + 0] = ar + Tlast * bg[0];
        out[3 * warp + 1] = ag + Tlast * bg[1];
        out[3 * warp + 2] = ab + Tlast * bg[2];
    }
}

extern "C" void kernel_launch(void* const* d_in, const int* in_sizes, int n_in,
                              void* d_out, int out_size) {
    const float* density    = (const float*)d_in[0];
    const float* rgb        = (const float*)d_in[1];
    const float* bg         = (const float*)d_in[2];
    const float* p_shift    = (const float*)d_in[3];
    const float* p_interval = (const float*)d_in[4];
    const int*   ray_id     = (const int*)d_in[5];

    const int M      = in_sizes[0];
    const int n_rays = out_size / 3;
    float* out = (float*)d_out;

    const int Mv4 = M / 4;             // elements covered by vec4 kernel
    {
        int threads = 256;
        int blocks = (Mv4 + threads - 1) / threads;
        if (blocks > 0) build_offsets_vec4<<<blocks, threads>>>(ray_id, M, n_rays);
        int rem_from = Mv4 * 4;
        if (rem_from < M) {
            int rem = M - rem_from;
            build_offsets_tail<<<(rem + 255) / 256, 256>>>(ray_id, M, n_rays, rem_from);
        }
    }
    {
        int threads = 256;             // 8 warps = 8 rays per block
        int blocks = (n_rays * 32 + threads - 1) / threads;
        composite_kernel<<<blocks, threads>>>(density, rgb, bg, p_shift,
                                              p_interval, out, n_rays);
    }
}

// round 5
// speedup vs baseline: 1.7720x; 1.3140x over previous
#include <cuda_runtime.h>

// DirectVoxGO volume rendering composite, R3: fully vectorized loads.
//   log2(1-alpha_i) = -interval * log2(1 + exp(density_i + shift))
//   w_i = P_{i-1} - P_i,  P = 2^(per-ray inclusive prefix of log2(1-alpha))
//   out[r] = sum w_i rgb_i + P_last * bg
//
// Kernel 1: per-ray start offsets from sorted ray_id (int4 + shfl for prev).
// Kernel 2: one warp per ray, 4 samples/thread, chunk base aligned down to 4
//           so density is 1 x LDG.128 and rgb is 3 x LDG.128 per thread.
//           Out-of-segment samples get l2t=0 => weight is exactly 0.

#define MAX_RAYS ((1 << 20))
__device__ int g_offsets[MAX_RAYS + 2];

__device__ __forceinline__ float f_ex2(float x) {
    float y; asm("ex2.approx.ftz.f32 %0, %1;" : "=f"(y) : "f"(x)); return y;
}
__device__ __forceinline__ float f_lg2(float x) {
    float y; asm("lg2.approx.ftz.f32 %0, %1;" : "=f"(y) : "f"(x)); return y;
}

// ---- Phase 1: offsets table ----
__global__ void __launch_bounds__(256)
build_offsets_vec4(const int* __restrict__ ray_id, int M, int n_rays) {
    const int i = blockIdx.x * blockDim.x + threadIdx.x;   // vec4 index
    const int e0 = i * 4;
    const bool active = (e0 < M);

    int4 v = make_int4(0, 0, 0, 0);
    if (active) v = reinterpret_cast<const int4*>(ray_id)[i];

    // previous element: last lane's v.w via shuffle; lane 0 loads it
    int prevw = __shfl_up_sync(0xffffffffu, v.w, 1);
    if (!active) return;

    int prev;
    if ((threadIdx.x & 31) == 0 || e0 == 0)
        prev = (e0 == 0) ? -1 : __ldg(&ray_id[e0 - 1]);
    else
        prev = prevw;

    int vals[4] = {v.x, v.y, v.z, v.w};
    #pragma unroll
    for (int j = 0; j < 4; ++j) {
        int cur = vals[j];
        if (cur != prev) {
            for (int r = prev + 1; r <= cur; ++r) g_offsets[r] = e0 + j;
        }
        prev = cur;
    }
    if (e0 + 3 == M - 1) {
        for (int r = prev + 1; r <= n_rays; ++r) g_offsets[r] = M;
    }
}

// tail-safe scalar version for M % 4 != 0 (unused for this shape)
__global__ void build_offsets_tail(const int* __restrict__ ray_id, int M, int n_rays, int from) {
    int i = from + blockIdx.x * blockDim.x + threadIdx.x;
    if (i >= M) return;
    int cur = ray_id[i];
    int prev = (i == 0) ? -1 : ray_id[i - 1];
    for (int r = prev + 1; r <= cur; ++r) g_offsets[r] = i;
    if (i == M - 1)
        for (int r = cur + 1; r <= n_rays; ++r) g_offsets[r] = M;
}

// ---- Phase 2: one warp per ray, 4 samples/thread, vectorized ----
__global__ void __launch_bounds__(256)
composite_kernel(const float* __restrict__ density,
                 const float* __restrict__ rgb,
                 const float* __restrict__ bg,
                 const float* __restrict__ p_shift,
                 const float* __restrict__ p_interval,
                 float* __restrict__ out,
                 int n_rays) {
    const int warp = (blockIdx.x * blockDim.x + threadIdx.x) >> 5;
    const int lane = threadIdx.x & 31;
    if (warp >= n_rays) return;

    const int start = g_offsets[warp];
    const int end   = g_offsets[warp + 1];

    const float shift = *p_shift;
    const float nInterval = -(*p_interval);
    const float L2E = 1.4426950408889634f;

    float carry = 0.f;                 // running log2(T) at chunk entry
    float ar = 0.f, ag = 0.f, ab = 0.f;

    // aligned chunk base: idx0 = base + lane*4 is always 4-aligned
    for (int base = (start & ~3); base < end; base += 128) {
        const int idx0 = base + lane * 4;
        const bool grp = (idx0 < end);    // group has at least one in-range element

        float4 d  = make_float4(0.f, 0.f, 0.f, 0.f);
        float4 c0 = d, c1 = d, c2 = d;
        if (grp) {
            d  = *reinterpret_cast<const float4*>(density + idx0);       // 16B aligned
            const float* cbase = rgb + 3 * idx0;                          // 16B aligned
            c0 = *reinterpret_cast<const float4*>(cbase);
            c1 = *reinterpret_cast<const float4*>(cbase + 4);
            c2 = *reinterpret_cast<const float4*>(cbase + 8);
        }

        // per-element log2(1-alpha); 0 outside [start, end)
        float dv[4] = {d.x, d.y, d.z, d.w};
        float l2t[4];
        #pragma unroll
        for (int j = 0; j < 4; ++j) {
            const int idx = idx0 + j;
            if (grp && idx >= start && idx < end) {
                float e = f_ex2((dv[j] + shift) * L2E);       // exp(x)
                l2t[j] = nInterval * f_lg2(1.f + e);          // <= 0
            } else {
                l2t[j] = 0.f;
            }
        }

        // thread-local inclusive prefix
        const float s0 = l2t[0];
        const float s1 = s0 + l2t[1];
        const float s2 = s1 + l2t[2];
        const float s3 = s2 + l2t[3];

        // warp scan of thread totals
        float inc = s3;
        #pragma unroll
        for (int off = 1; off < 32; off <<= 1) {
            float v = __shfl_up_sync(0xffffffffu, inc, off);
            if (lane >= off) inc += v;
        }
        const float excl = carry + (inc - s3);

        // transmittance samples; identical exponents => exact zero weights
        const float Pm1 = f_ex2(excl);
        const float P0  = f_ex2(excl + s0);
        const float P1  = f_ex2(excl + s1);
        const float P2  = f_ex2(excl + s2);
        const float P3  = f_ex2(excl + s3);

        const float w0 = Pm1 - P0;
        const float w1 = P0 - P1;
        const float w2 = P1 - P2;
        const float w3 = P2 - P3;

        // rgb layout: c0=(r0,g0,b0,r1) c1=(g1,b1,r2,g2) c2=(b2,r3,g3,b3)
        ar = fmaf(w0, c0.x, ar);  ag = fmaf(w0, c0.y, ag);  ab = fmaf(w0, c0.z, ab);
        ar = fmaf(w1, c0.w, ar);  ag = fmaf(w1, c1.x, ag);  ab = fmaf(w1, c1.y, ab);
        ar = fmaf(w2, c1.z, ar);  ag = fmaf(w2, c1.w, ag);  ab = fmaf(w2, c2.x, ab);
        ar = fmaf(w3, c2.y, ar);  ag = fmaf(w3, c2.z, ag);  ab = fmaf(w3, c2.w, ab);

        carry += __shfl_sync(0xffffffffu, inc, 31);
    }

    // warp reduction
    #pragma unroll
    for (int off = 16; off; off >>= 1) {
        ar += __shfl_xor_sync(0xffffffffu, ar, off);
        ag += __shfl_xor_sync(0xffffffffu, ag, off);
        ab += __shfl_xor_sync(0xffffffffu, ab, off);
    }

    if (lane == 0) {
        const float Tlast = f_ex2(carry);
        out[3 * warp + 0] = ar + Tlast * bg[0];
        out[3 * warp + 1] = ag + Tlast * bg[1];
        out[3 * warp + 2] = ab + Tlast * bg[2];
    }
}

extern "C" void kernel_launch(void* const* d_in, const int* in_sizes, int n_in,
                              void* d_out, int out_size) {
    const float* density    = (const float*)d_in[0];
    const float* rgb        = (const float*)d_in[1];
    const float* bg         = (const float*)d_in[2];
    const float* p_shift    = (const float*)d_in[3];
    const float* p_interval = (const float*)d_in[4];
    const int*   ray_id     = (const int*)d_in[5];

    const int M      = in_sizes[0];
    const int n_rays = out_size / 3;
    float* out = (float*)d_out;

    const int Mv4 = M / 4;
    {
        int threads = 256;
        int blocks = (Mv4 + threads - 1) / threads;
        if (blocks > 0) build_offsets_vec4<<<blocks, threads>>>(ray_id, M, n_rays);
        int rem_from = Mv4 * 4;
        if (rem_from < M) {
            int rem = M - rem_from;
            build_offsets_tail<<<(rem + 255) / 256, 256>>>(ray_id, M, n_rays, rem_from);
        }
    }
    {
        int threads = 256;             // 8 warps = 8 rays per block
        int blocks = (n_rays * 32 + threads - 1) / threads;
        composite_kernel<<<blocks, threads>>>(density, rgb, bg, p_shift,
                                              p_interval, out, n_rays);
    }
}